// round 5
// baseline (speedup 1.0000x reference)
#include <cuda_runtime.h>
#include <math.h>

#define BATCH 64
#define HID   1024
#define INP   1024

// ---------------- scratch (static device globals; no allocation) -------------
__device__ float g_part[4][6][BATCH][HID];   // split-K GEMM partials
__device__ float g_f [BATCH][HID];           // sigmoid(f_tilda)
__device__ float g_a [BATCH][HID];           // i_prime * v
__device__ float g_o [BATCH][HID];           // sigmoid(o_tilda)
__device__ float g_k [BATCH][HID];           // k_t (scaled by 1/32)
__device__ float g_q [BATCH][HID];           // q_t
__device__ float g_nq[BATCH];                // sum_j n_t * q_t

struct WPtrs {
    const float* W[6];
    const float* b[6];
};

// ---------------- kernel 1: six fused GEMMs, split-K=4 -----------------------
// out_part[z][g][m][n] = sum_{k in chunk z} x[m][k] * W_g[n][k]
// BM=64 (all batch), BN=64, BK=32, 256 threads, 4x4 microtile per thread.
__global__ void __launch_bounds__(256) gemm6_kernel(const float* __restrict__ x, WPtrs wp)
{
    const int ntile = blockIdx.x;   // 0..15
    const int g     = blockIdx.y;   // 0..5
    const int z     = blockIdx.z;   // 0..3
    const float* __restrict__ W = wp.W[g];

    __shared__ float xs[32][68];    // [kk][m], padded
    __shared__ float ws[32][68];    // [kk][n], padded

    const int tid = threadIdx.x;
    const int ty  = tid >> 4;       // 0..15  (m groups)
    const int tx  = tid & 15;       // 0..15  (n groups)
    const int n0  = ntile * 64;

    float acc[4][4];
#pragma unroll
    for (int i = 0; i < 4; ++i)
#pragma unroll
        for (int j = 0; j < 4; ++j) acc[i][j] = 0.0f;

    for (int kt = 0; kt < 8; ++kt) {
        const int k0 = z * 256 + kt * 32;
        // load 64x32 tiles of x and W (transposed into smem)
#pragma unroll
        for (int i = 0; i < 2; ++i) {
            int f  = tid + i * 256;       // 0..511 -> 512 float4 per tile
            int m  = f >> 3;              // 0..63
            int kc = (f & 7) * 4;         // 0,4,...,28
            float4 xv = *(const float4*)(x + (size_t)m * INP + k0 + kc);
            xs[kc + 0][m] = xv.x; xs[kc + 1][m] = xv.y;
            xs[kc + 2][m] = xv.z; xs[kc + 3][m] = xv.w;
            float4 wv = *(const float4*)(W + (size_t)(n0 + m) * INP + k0 + kc);
            ws[kc + 0][m] = wv.x; ws[kc + 1][m] = wv.y;
            ws[kc + 2][m] = wv.z; ws[kc + 3][m] = wv.w;
        }
        __syncthreads();
#pragma unroll
        for (int kk = 0; kk < 32; ++kk) {
            float4 av = *(const float4*)&xs[kk][ty * 4];
            float4 bv = *(const float4*)&ws[kk][tx * 4];
            float a4[4] = {av.x, av.y, av.z, av.w};
            float b4[4] = {bv.x, bv.y, bv.z, bv.w};
#pragma unroll
            for (int i = 0; i < 4; ++i)
#pragma unroll
                for (int j = 0; j < 4; ++j)
                    acc[i][j] = fmaf(a4[i], b4[j], acc[i][j]);
        }
        __syncthreads();
    }

    float* out = &g_part[z][g][0][0];
#pragma unroll
    for (int i = 0; i < 4; ++i) {
        int m = ty * 4 + i;
#pragma unroll
        for (int j = 0; j < 4; ++j) {
            out[(size_t)m * HID + n0 + tx * 4 + j] = acc[i][j];
        }
    }
}

// ---------------- kernel 2: gate pointwise + per-batch reduction -------------
__global__ void __launch_bounds__(256) pointwise_kernel(
    const float* __restrict__ nprev, const float* __restrict__ mprev_in,
    WPtrs wp, float* __restrict__ out_n, float* __restrict__ out_m)
{
    const int b   = blockIdx.x;
    const int tid = threadIdx.x;
    float local_nq = 0.0f;

#pragma unroll
    for (int t = 0; t < 4; ++t) {
        const int h = tid + t * 256;
        float s[6];
#pragma unroll
        for (int g = 0; g < 6; ++g) {
            float v = wp.b[g][h];
#pragma unroll
            for (int zz = 0; zz < 4; ++zz) v += g_part[zz][g][b][h];
            s[g] = v;
        }
        const float it   = s[0];
        const float ftil = s[1];
        const float otil = s[2];
        const float qv   = s[3];
        const float kv   = s[4] * (1.0f / 32.0f);   // / sqrt(1024)
        const float vv   = s[5];

        const float ft   = 1.0f / (1.0f + expf(-ftil));
        // log(sigmoid(ftil)), numerically stable
        const float lgf  = (ftil >= 0.0f) ? -log1pf(expf(-ftil))
                                          : (ftil - log1pf(expf(ftil)));
        const float mp = mprev_in[(size_t)b * HID + h];
        const float mt = fmaxf(lgf + mp, it);
        const float ip = expf(it - mt);
        const float nt = ft * nprev[(size_t)b * HID + h] + ip * kv;

        out_n[(size_t)b * HID + h] = nt;
        out_m[(size_t)b * HID + h] = mt;
        g_f[b][h] = ft;
        g_a[b][h] = ip * vv;
        g_o[b][h] = 1.0f / (1.0f + expf(-otil));
        g_k[b][h] = kv;
        g_q[b][h] = qv;
        local_nq += nt * qv;
    }

    // block reduce local_nq (256 threads = 8 warps)
    __shared__ float red[8];
#pragma unroll
    for (int off = 16; off > 0; off >>= 1)
        local_nq += __shfl_xor_sync(0xFFFFFFFFu, local_nq, off);
    if ((tid & 31) == 0) red[tid >> 5] = local_nq;
    __syncthreads();
    if (tid < 8) {
        float v = red[tid];
#pragma unroll
        for (int off = 4; off > 0; off >>= 1)
            v += __shfl_xor_sync(0xFFu, v, off);
        if (tid == 0) g_nq[b] = v;
    }
}

// ---------------- kernel 3: fused fast-weight update + readout ---------------
// One warp per C row; 16 rows per block; k,q cached in smem per block.
__global__ void __launch_bounds__(512) update_kernel(
    const float* __restrict__ C, float* __restrict__ outC, float* __restrict__ outH)
{
    __shared__ float sk[HID];
    __shared__ float sq[HID];

    const int b  = blockIdx.x >> 6;          // 64 blocks per batch
    const int r0 = (blockIdx.x & 63) << 4;   // 16 rows per block

    for (int i = threadIdx.x; i < HID; i += 512) {
        sk[i] = g_k[b][i];
        sq[i] = g_q[b][i];
    }
    __syncthreads();

    const int w    = threadIdx.x >> 5;
    const int lane = threadIdx.x & 31;
    const int r    = r0 + w;

    const float f = g_f[b][r];
    const float a = g_a[b][r];

    const size_t base = ((size_t)b * HID + r) * HID;
    const float4* __restrict__ Crow = (const float4*)(C + base);
    float4* __restrict__ Orow       = (float4*)(outC + base);
    const float4* __restrict__ k4p  = (const float4*)sk;
    const float4* __restrict__ q4p  = (const float4*)sq;

    float acc = 0.0f;
#pragma unroll
    for (int t = 0; t < 8; ++t) {
        const int j  = lane + t * 32;        // float4 index, coalesced
        float4 c  = Crow[j];
        float4 k4 = k4p[j];
        float4 q4 = q4p[j];
        float4 ct;
        ct.x = fmaf(f, c.x, a * k4.x);
        ct.y = fmaf(f, c.y, a * k4.y);
        ct.z = fmaf(f, c.z, a * k4.z);
        ct.w = fmaf(f, c.w, a * k4.w);
        Orow[j] = ct;
        acc = fmaf(ct.x, q4.x, acc);
        acc = fmaf(ct.y, q4.y, acc);
        acc = fmaf(ct.z, q4.z, acc);
        acc = fmaf(ct.w, q4.w, acc);
    }
#pragma unroll
    for (int off = 16; off > 0; off >>= 1)
        acc += __shfl_xor_sync(0xFFFFFFFFu, acc, off);

    if (lane == 0) {
        const float div = fmaxf(fabsf(g_nq[b]), 1.0f);
        outH[(size_t)b * HID + r] = g_o[b][r] * acc / div;
    }
}

// ---------------- launch ------------------------------------------------------
extern "C" void kernel_launch(void* const* d_in, const int* in_sizes, int n_in,
                              void* d_out, int out_size)
{
    const float* x     = (const float*)d_in[0];
    const float* Cin   = (const float*)d_in[1];
    const float* nprev = (const float*)d_in[2];
    const float* mprev = (const float*)d_in[3];

    WPtrs wp;
    for (int g = 0; g < 6; ++g) {
        wp.W[g] = (const float*)d_in[4 + 2 * g];
        wp.b[g] = (const float*)d_in[5 + 2 * g];
    }

    float* out  = (float*)d_out;
    float* outH = out;                                       // (64,1024)
    float* outC = out + (size_t)BATCH * HID;                 // (64,1024,1024)
    float* outN = outC + (size_t)BATCH * HID * HID;          // (64,1024)
    float* outM = outN + (size_t)BATCH * HID;                // (64,1024)

    gemm6_kernel<<<dim3(16, 6, 4), 256>>>(x, wp);
    pointwise_kernel<<<BATCH, 256>>>(nprev, mprev, wp, outN, outM);
    update_kernel<<<BATCH * (HID / 16), 512>>>(Cin, outC, outH);
}